// round 10
// baseline (speedup 1.0000x reference)
#include <cuda_runtime.h>

// Problem constants
#define BB 128
#define SS 2048
#define DD 128
#define YY 26

typedef unsigned long long u64;

// ---- packed f32x2 helpers (each = two independent .rn ops; bit-exact) ----
__device__ __forceinline__ u64 pack2(float x, float y) {
    u64 r; asm("mov.b64 %0, {%1,%2};" : "=l"(r) : "f"(x), "f"(y)); return r;
}
__device__ __forceinline__ float2 unpack2(u64 u) {
    float2 f; asm("mov.b64 {%0,%1}, %2;" : "=f"(f.x), "=f"(f.y) : "l"(u)); return f;
}
__device__ __forceinline__ u64 add2(u64 a, u64 b) {
    u64 d; asm("add.rn.f32x2 %0, %1, %2;" : "=l"(d) : "l"(a), "l"(b)); return d;
}
__device__ __forceinline__ u64 fma2(u64 a, u64 b, u64 c) {
    u64 d; asm("fma.rn.f32x2 %0, %1, %2, %3;" : "=l"(d) : "l"(a), "l"(b), "l"(c)); return d;
}

// ---------------------------------------------------------------------------
// Emit TWO rows: e[y] = sum_d x[d]*W[d][y], verified cuBLAS sliced1x4 ordering
// (slice z over chunks k=32t+8z ascending, FMA ascending k, ((s0+s1)+s2)+s3).
// Weight LDS loaded once per k feeds both rows' chains (halves LDS traffic);
// each row's scalar op sequence is identical to the verified single-row kernel.
// ---------------------------------------------------------------------------
__device__ __forceinline__ void emit_row2(const float* __restrict__ xrowA,
                                          const float* __restrict__ xrowB,
                                          const float* __restrict__ Ws,
                                          float* __restrict__ dstA,
                                          float* __restrict__ dstB) {
    const float4* xrA = (const float4*)xrowA;
    const float4* xrB = (const float4*)xrowB;
    u64 rA[13], sA[13], rB[13], sB[13];
#pragma unroll
    for (int z = 0; z < 4; z++) {
#pragma unroll
        for (int k = 0; k < 13; k++) { sA[k] = 0ULL; sB[k] = 0ULL; }
#pragma unroll
        for (int t = 0; t < 4; t++) {
            int c = 8 * t + 2 * z;  // float4 index; chunk k = 32t+8z
            float4 xa = xrA[c], xb = xrA[c + 1];
            float4 ya = xrB[c], yb = xrB[c + 1];
            float xs[8] = {xa.x, xa.y, xa.z, xa.w, xb.x, xb.y, xb.z, xb.w};
            float ys[8] = {ya.x, ya.y, ya.z, ya.w, yb.x, yb.y, yb.z, yb.w};
#pragma unroll
            for (int kk = 0; kk < 8; kk++) {
                u64 xx = pack2(xs[kk], xs[kk]);
                u64 yy = pack2(ys[kk], ys[kk]);
                const u64* wr = (const u64*)(Ws + (c * 4 + kk) * 32);
#pragma unroll
                for (int j = 0; j < 13; j++) {
                    u64 w = wr[j];
                    sA[j] = fma2(xx, w, sA[j]);
                    sB[j] = fma2(yy, w, sB[j]);
                }
            }
        }
#pragma unroll
        for (int k = 0; k < 13; k++) {
            rA[k] = (z == 0) ? sA[k] : add2(rA[k], sA[k]);
            rB[k] = (z == 0) ? sB[k] : add2(rB[k], sB[k]);
        }
    }
    float2* dA = (float2*)dstA;
    float2* dB = (float2*)dstB;
#pragma unroll
    for (int k = 0; k < 13; k++) { dA[k] = unpack2(rA[k]); dB[k] = unpack2(rB[k]); }
}

// ---------------------------------------------------------------------------
// Value-only max over 26 (exact; any combine order gives jnp.max bits).
// ---------------------------------------------------------------------------
__device__ __forceinline__ float max26(const float2* v) {
    float m1[13];
#pragma unroll
    for (int k = 0; k < 13; k++) m1[k] = fmaxf(v[k].x, v[k].y);
    float m2[7];
#pragma unroll
    for (int k = 0; k < 6; k++) m2[k] = fmaxf(m1[2 * k], m1[2 * k + 1]);
    m2[6] = m1[12];
    float a = fmaxf(m2[0], m2[1]);
    float b = fmaxf(m2[2], m2[3]);
    float c = fmaxf(m2[4], m2[5]);
    return fmaxf(fmaxf(a, b), fmaxf(c, m2[6]));
}

// Full first-index argmax (keep-left on >=, left covers lower indices).
__device__ __forceinline__ void argmax26p(const float2* v2, float& mv, int& mi) {
    float m1[13]; int i1[13];
#pragma unroll
    for (int k = 0; k < 13; k++) {
        float lo = v2[k].x, hi = v2[k].y;
        m1[k] = fmaxf(lo, hi);
        i1[k] = (lo >= hi) ? (2 * k) : (2 * k + 1);
    }
    float m2[7]; int i2[7];
#pragma unroll
    for (int k = 0; k < 6; k++) {
        m2[k] = fmaxf(m1[2 * k], m1[2 * k + 1]);
        i2[k] = (m1[2 * k] >= m1[2 * k + 1]) ? i1[2 * k] : i1[2 * k + 1];
    }
    m2[6] = m1[12]; i2[6] = i1[12];
    float m3[4]; int i3[4];
#pragma unroll
    for (int k = 0; k < 3; k++) {
        m3[k] = fmaxf(m2[2 * k], m2[2 * k + 1]);
        i3[k] = (m2[2 * k] >= m2[2 * k + 1]) ? i2[2 * k] : i2[2 * k + 1];
    }
    m3[3] = m2[6]; i3[3] = i2[6];
    float a = fmaxf(m3[0], m3[1]);
    int ia = (m3[0] >= m3[1]) ? i3[0] : i3[1];
    float bq = fmaxf(m3[2], m3[3]);
    int ib = (m3[2] >= m3[3]) ? i3[2] : i3[3];
    mv = fmaxf(a, bq);
    mi = (a >= bq) ? ia : ib;
}

// ---------------------------------------------------------------------------
// bp for one (i, y1=lane): first-index argmax over yp of (e[yp]+T[yp][y1])+l[yp]
// Serial ascending scan with strict > == jnp.argmax first-occurrence.
// ---------------------------------------------------------------------------
__device__ __forceinline__ int bp_argmax(const float* __restrict__ erow,
                                         const float* __restrict__ lrow,
                                         const u64* __restrict__ tcc) {
    float2 v[13];
    const float4* e4 = (const float4*)erow;
    const float4* l4 = (const float4*)lrow;
#pragma unroll
    for (int j = 0; j < 7; j++) {
        float4 e = e4[j];
        float4 l = l4[j];
        u64 a = add2(pack2(e.x, e.y), tcc[2 * j]);
        v[2 * j] = unpack2(add2(a, pack2(l.x, l.y)));
        if (2 * j + 1 < 13) {
            u64 bq = add2(pack2(e.z, e.w), tcc[2 * j + 1]);
            v[2 * j + 1] = unpack2(add2(bq, pack2(l.z, l.w)));
        }
    }
    float best = v[0].x;
    int idx = 0;
#pragma unroll
    for (int k = 0; k < 13; k++) {
        float lo = v[k].x, hi = v[k].y;
        if (k > 0 && lo > best) { best = lo; idx = 2 * k; }
        if (hi > best) { best = hi; idx = 2 * k + 1; }
    }
    return idx;
}

// ---------------------------------------------------------------------------
// Shared layout (bytes) — identical to the verified R8 kernel:
//   ebuf 3*128*32f @0 | lring 384*32f @49152 | Ws 128*32f @98304
//   Tt 32*32f @114688 | bp 2049*32B @118784 | maps @184352
//   path @185376 | entries @187424
// ---------------------------------------------------------------------------
#define OFF_EBUF 0
#define OFF_LRING 49152
#define OFF_WS 98304
#define OFF_TT 114688
#define OFF_BP 118784
#define OFF_MAPS 184352
#define OFF_PATH 185376
#define OFF_ENT 187424
#define SMEM_TOTAL 187552

// Warp roles (8 warps):
//   wid 7 : scan warp (highest arbiter priority; SMSP 3)
//   wid 3 : idle during phases (keeps SMSP 3 clear for the scan warp)
//   wid 0,1 : emit workers (2 rows/thread, 64 threads -> 128 rows)
//   wid 2,4,5,6 : bp workers (32 rows each)
__global__ void __launch_bounds__(256, 1) crf_kernel(const float* __restrict__ X,
                                                     const float* __restrict__ W,
                                                     const float* __restrict__ Tm,
                                                     float* __restrict__ out) {
    extern __shared__ unsigned char smx[];
    float* ebuf = (float*)(smx + OFF_EBUF);
    float* lring = (float*)(smx + OFF_LRING);
    float* Ws = (float*)(smx + OFF_WS);
    float* Tt = (float*)(smx + OFF_TT);
    unsigned char* bp = smx + OFF_BP;
    unsigned char* maps = smx + OFF_MAPS;
    unsigned char* path = smx + OFF_PATH;
    int* entries = (int*)(smx + OFF_ENT);

    int tid = threadIdx.x;
    int wid = tid >> 5;
    int lane = tid & 31;
    int b = blockIdx.x;
    const float* Xb = X + (size_t)b * SS * DD;

    bool is_scan = (wid == 7);
    bool is_idle = (wid == 3);
    bool is_emit = (wid == 0) || (wid == 1);
    // bp worker index 0..3 for wids {2,4,5,6}
    int bpw = (wid == 2) ? 0 : (wid >= 4 && wid <= 6) ? (wid - 3) : -1;

    // ---- init ----
    for (int j = tid; j < 128 * 32; j += 256) {
        int k = j >> 5, y = j & 31;
        Ws[j] = (y < YY) ? W[k * YY + y] : 0.f;
    }
    for (int j = tid; j < 32 * 32; j += 256) {
        int ln = j >> 5, yp = j & 31;
        Tt[j] = (ln < YY && yp < YY) ? Tm[yp * YY + ln] : 0.f;
    }
    if (tid < 32) lring[tid] = 0.f;                                  // l[0]=0
    if (tid < 32) bp[2048 * 32 + tid] = (unsigned char)(tid < YY ? tid : 0);
    __syncthreads();

    // ---- prologue: emit tile 0 into ebuf[0] (warps 0-1, 2 rows/thread) ----
    if (tid < 64) {
        emit_row2(Xb + (size_t)tid * DD, Xb + (size_t)(tid + 64) * DD, Ws,
                  ebuf + tid * 32, ebuf + (tid + 64) * 32);
    }
    __syncthreads();

    // per-lane T column as packed pairs (used by scan + bp warps)
    u64 tcc[13];
    {
        const float4* t4 = (const float4*)(Tt + lane * 32);
#pragma unroll
        for (int j = 0; j < 7; j++) {
            float4 t = t4[j];
            tcc[2 * j] = pack2(t.x, t.y);
            if (2 * j + 1 < 13) tcc[2 * j + 1] = pack2(t.z, t.w);
        }
    }

    // scan-warp persistent state
    u64 a2[13];
    float* lw = lring + 32;        // write ptr: row 1
    const float* lr = lring;       // read ptr: row 0
    if (is_scan) {
        const float4* e4 = (const float4*)ebuf;  // e[0]
#pragma unroll
        for (int j = 0; j < 7; j++) {
            float4 e = e4[j];
            a2[2 * j] = add2(pack2(e.x, e.y), tcc[2 * j]);
            if (2 * j + 1 < 13) a2[2 * j + 1] = add2(pack2(e.z, e.w), tcc[2 * j + 1]);
        }
    }

    // =========================== 16 phases ===========================
    for (int p = 0; p < 16; p++) {
        if (is_scan) {
            // scan tile p: steps i in [max(1, p*128), p*128+128)
            const float* etb = ebuf + (p % 3) * 4096;
            int i0 = (p == 0) ? 1 : p * 128;
            int i1 = p * 128 + 128;
#pragma unroll 2
            for (int i = i0; i < i1; i++) {
                // v = a + l  (critical chain)
                float2 v[13];
                const float4* l4 = (const float4*)lr;
#pragma unroll
                for (int j = 0; j < 7; j++) {
                    float4 l = l4[j];
                    v[2 * j] = unpack2(add2(a2[2 * j], pack2(l.x, l.y)));
                    if (2 * j + 1 < 13)
                        v[2 * j + 1] = unpack2(add2(a2[2 * j + 1], pack2(l.z, l.w)));
                }
                float m = max26(v);
                lw[lane] = m;  // l[i]
                // a_next = e[i] + Tc  (off the chain; hides STS->LDS forward)
                const float4* e4 = (const float4*)(etb + (i & 127) * 32);
#pragma unroll
                for (int j = 0; j < 7; j++) {
                    float4 e = e4[j];
                    a2[2 * j] = add2(pack2(e.x, e.y), tcc[2 * j]);
                    if (2 * j + 1 < 13)
                        a2[2 * j + 1] = add2(pack2(e.z, e.w), tcc[2 * j + 1]);
                }
                __syncwarp();
                lr = lw;
                lw += 32;
                if (lw == lring + 384 * 32) lw = lring;
            }
        } else if (!is_idle) {
            // --- bp workers: backpointers for tile p-1 ---
            if (p >= 1 && bpw >= 0) {
                int tt = p - 1;
                for (int r = bpw; r < 128; r += 4) {
                    int i = tt * 128 + r;
                    if (i > 0) {
                        const float* erow = (r > 0)
                            ? (ebuf + (tt % 3) * 4096 + (r - 1) * 32)
                            : (ebuf + ((tt + 2) % 3) * 4096 + 127 * 32);
                        const float* lrow = lring + ((i - 1) % 384) * 32;
                        int idx = bp_argmax(erow, lrow, tcc);
                        if (lane < YY) bp[i * 32 + lane] = (unsigned char)idx;
                    }
                }
            }
            // boundary e-row reads above must precede the emit overwrite below
            asm volatile("bar.sync 1, 192;" ::: "memory");
            // --- emit workers: tile p+1 (2 rows/thread) ---
            if (p + 1 < 16 && is_emit) {
                int cid = tid;  // wid 0,1 -> tid 0..63
                const float* xa = Xb + (size_t)((p + 1) * 128 + cid) * DD;
                const float* xb = Xb + (size_t)((p + 1) * 128 + cid + 64) * DD;
                float* da = ebuf + ((p + 1) % 3) * 4096 + cid * 32;
                float* db = ebuf + ((p + 1) % 3) * 4096 + (cid + 64) * 32;
                emit_row2(xa, xb, Ws, da, db);
            }
        }
        __syncthreads();
    }

    // ====================== epilogue ======================
    if (is_scan) {
        // last = argmax(em[2047] + lookup[2047])  (em first, reference order)
        const float4* e4 = (const float4*)(ebuf + 0 * 4096 + 127 * 32);  // tile15->buf0
        const float4* l4 = (const float4*)(lring + 127 * 32);            // 2047%384=127
        float2 vv[13];
#pragma unroll
        for (int j = 0; j < 7; j++) {
            float4 e = e4[j];
            float4 l = l4[j];
            vv[2 * j] = unpack2(add2(pack2(e.x, e.y), pack2(l.x, l.y)));
            if (2 * j + 1 < 13)
                vv[2 * j + 1] = unpack2(add2(pack2(e.z, e.w), pack2(l.z, l.w)));
        }
        float mm; int last;
        argmax26p(vv, mm, last);
        if (lane == 0) entries[31] = last;
    } else if (bpw >= 0) {
        // bp for tile 15
        int tt = 15;
        for (int r = bpw; r < 128; r += 4) {
            int i = tt * 128 + r;
            const float* erow = (r > 0)
                ? (ebuf + (tt % 3) * 4096 + (r - 1) * 32)
                : (ebuf + ((tt + 2) % 3) * 4096 + 127 * 32);
            const float* lrow = lring + ((i - 1) % 384) * 32;
            int idx = bp_argmax(erow, lrow, tcc);
            if (lane < YY) bp[i * 32 + lane] = (unsigned char)idx;
        }
    }
    __syncthreads();

    // ===== Phase A: per-chunk composed maps (8 warps x 4 chunks of 64) =====
    for (int q = 0; q < 4; q++) {
        int c = wid * 4 + q;
        if (lane < YY) {
            int y = lane;
            int r = (c * 64 + 64) * 32;
            for (int k = 0; k < 64; k++) { y = bp[r + y]; r -= 32; }
            maps[c * 32 + lane] = (unsigned char)y;
        }
    }
    __syncthreads();

    // ===== Phase B: chunk entry labels (serial, 1 thread) =====
    if (tid == 0) {
        int e = entries[31];
        for (int c = 31; c >= 1; c--) {
            e = maps[c * 32 + e];
            entries[c - 1] = e;
        }
    }
    __syncthreads();

    // ===== Phase C: re-chase chunks in parallel (warp 0, 1 chunk/lane) =====
    if (wid == 0) {
        int c = lane;
        int y = entries[c];
        int r = (c * 64 + 64) * 32;
        for (int k = 63; k >= 0; k--) {
            y = bp[r + y];
            r -= 32;
            path[c * 64 + k] = (unsigned char)y;
        }
    }
    __syncthreads();

    // ===== Phase D: one-hot output (256 threads, float2 rows) =====
    float* ob = out + (size_t)b * SS * YY;
    for (int i = tid; i < SS; i += 256) {
        int lbl = path[i];
        float2* orow = (float2*)(ob + (size_t)i * YY);
#pragma unroll
        for (int k = 0; k < 13; k++) {
            float2 w;
            w.x = (2 * k == lbl) ? 1.f : 0.f;
            w.y = (2 * k + 1 == lbl) ? 1.f : 0.f;
            orow[k] = w;
        }
    }
}

// ---------------------------------------------------------------------------
extern "C" void kernel_launch(void* const* d_in, const int* in_sizes, int n_in,
                              void* d_out, int out_size) {
    const float* X = (const float*)d_in[0];   // [B,S,D]
    const float* W = (const float*)d_in[1];   // [D,Y]
    const float* T = (const float*)d_in[2];   // [Y,Y]
    float* out = (float*)d_out;               // [B,S,Y] fp32

    cudaFuncSetAttribute(crf_kernel,
                         cudaFuncAttributeMaxDynamicSharedMemorySize, SMEM_TOTAL);
    crf_kernel<<<BB, 256, SMEM_TOTAL>>>(X, W, T, out);
}

// round 13
// speedup vs baseline: 1.1538x; 1.1538x over previous
#include <cuda_runtime.h>

// Problem constants
#define BB 128
#define SS 2048
#define DD 128
#define YY 26

typedef unsigned long long u64;

// ---- packed f32x2 helpers (each = two independent .rn ops; bit-exact) ----
__device__ __forceinline__ u64 pack2(float x, float y) {
    u64 r; asm("mov.b64 %0, {%1,%2};" : "=l"(r) : "f"(x), "f"(y)); return r;
}
__device__ __forceinline__ float2 unpack2(u64 u) {
    float2 f; asm("mov.b64 {%0,%1}, %2;" : "=f"(f.x), "=f"(f.y) : "l"(u)); return f;
}
__device__ __forceinline__ u64 add2(u64 a, u64 b) {
    u64 d; asm("add.rn.f32x2 %0, %1, %2;" : "=l"(d) : "l"(a), "l"(b)); return d;
}
__device__ __forceinline__ u64 fma2(u64 a, u64 b, u64 c) {
    u64 d; asm("fma.rn.f32x2 %0, %1, %2, %3;" : "=l"(d) : "l"(a), "l"(b), "l"(c)); return d;
}

// ---------------------------------------------------------------------------
// Emit ONE row: e[y] = sum_d x[d]*W[d][y], verified cuBLAS sliced1x4 ordering
// (slice z over chunks k=32t+8z ascending t, FMA ascending k, ((s0+s1)+s2)+s3).
// Weights read as 7 LDS.128 per k-element (same values/order as the verified
// 13-LDS.64 version -> bit-exact, ~45% fewer LDS instructions).
// ---------------------------------------------------------------------------
__device__ __forceinline__ void emit_row(const float* __restrict__ xrow,
                                         const float* __restrict__ Ws,
                                         float* __restrict__ dst) {
    const float4* xr = (const float4*)xrow;
    u64 r2[13], s2[13];
#pragma unroll
    for (int z = 0; z < 4; z++) {
#pragma unroll
        for (int k = 0; k < 13; k++) s2[k] = 0ULL;
#pragma unroll
        for (int t = 0; t < 4; t++) {
            int c = 8 * t + 2 * z;  // float4 index; chunk k = 32t+8z
            float4 xa = xr[c];
            float4 xb = xr[c + 1];
            float xs[8] = {xa.x, xa.y, xa.z, xa.w, xb.x, xb.y, xb.z, xb.w};
#pragma unroll
            for (int kk = 0; kk < 8; kk++) {
                u64 xx = pack2(xs[kk], xs[kk]);
                const float4* w4 = (const float4*)(Ws + (c * 4 + kk) * 32);
#pragma unroll
                for (int q = 0; q < 7; q++) {
                    float4 w = w4[q];
                    s2[2 * q] = fma2(xx, pack2(w.x, w.y), s2[2 * q]);
                    if (2 * q + 1 < 13)
                        s2[2 * q + 1] = fma2(xx, pack2(w.z, w.w), s2[2 * q + 1]);
                }
            }
        }
#pragma unroll
        for (int k = 0; k < 13; k++) r2[k] = (z == 0) ? s2[k] : add2(r2[k], s2[k]);
    }
    float2* d2 = (float2*)dst;
#pragma unroll
    for (int k = 0; k < 13; k++) d2[k] = unpack2(r2[k]);
}

// ---------------------------------------------------------------------------
// Value-only max over 26 (exact; any combine order gives jnp.max bits).
// ---------------------------------------------------------------------------
__device__ __forceinline__ float max26(const float2* v) {
    float m1[13];
#pragma unroll
    for (int k = 0; k < 13; k++) m1[k] = fmaxf(v[k].x, v[k].y);
    float m2[7];
#pragma unroll
    for (int k = 0; k < 6; k++) m2[k] = fmaxf(m1[2 * k], m1[2 * k + 1]);
    m2[6] = m1[12];
    float a = fmaxf(m2[0], m2[1]);
    float b = fmaxf(m2[2], m2[3]);
    float c = fmaxf(m2[4], m2[5]);
    return fmaxf(fmaxf(a, b), fmaxf(c, m2[6]));
}

// Full first-index argmax (keep-left on >=, left covers lower indices).
__device__ __forceinline__ void argmax26p(const float2* v2, float& mv, int& mi) {
    float m1[13]; int i1[13];
#pragma unroll
    for (int k = 0; k < 13; k++) {
        float lo = v2[k].x, hi = v2[k].y;
        m1[k] = fmaxf(lo, hi);
        i1[k] = (lo >= hi) ? (2 * k) : (2 * k + 1);
    }
    float m2[7]; int i2[7];
#pragma unroll
    for (int k = 0; k < 6; k++) {
        m2[k] = fmaxf(m1[2 * k], m1[2 * k + 1]);
        i2[k] = (m1[2 * k] >= m1[2 * k + 1]) ? i1[2 * k] : i1[2 * k + 1];
    }
    m2[6] = m1[12]; i2[6] = i1[12];
    float m3[4]; int i3[4];
#pragma unroll
    for (int k = 0; k < 3; k++) {
        m3[k] = fmaxf(m2[2 * k], m2[2 * k + 1]);
        i3[k] = (m2[2 * k] >= m2[2 * k + 1]) ? i2[2 * k] : i2[2 * k + 1];
    }
    m3[3] = m2[6]; i3[3] = i2[6];
    float a = fmaxf(m3[0], m3[1]);
    int ia = (m3[0] >= m3[1]) ? i3[0] : i3[1];
    float bq = fmaxf(m3[2], m3[3]);
    int ib = (m3[2] >= m3[3]) ? i3[2] : i3[3];
    mv = fmaxf(a, bq);
    mi = (a >= bq) ? ia : ib;
}

// ---------------------------------------------------------------------------
// bp for one (i, y1=lane): first-index argmax over yp of (e[yp]+T[yp][y1])+l[yp]
// Serial ascending scan with strict > == jnp.argmax first-occurrence.
// ---------------------------------------------------------------------------
__device__ __forceinline__ int bp_argmax(const float* __restrict__ erow,
                                         const float* __restrict__ lrow,
                                         const u64* __restrict__ tcc) {
    float2 v[13];
    const float4* e4 = (const float4*)erow;
    const float4* l4 = (const float4*)lrow;
#pragma unroll
    for (int j = 0; j < 7; j++) {
        float4 e = e4[j];
        float4 l = l4[j];
        u64 a = add2(pack2(e.x, e.y), tcc[2 * j]);
        v[2 * j] = unpack2(add2(a, pack2(l.x, l.y)));
        if (2 * j + 1 < 13) {
            u64 bq = add2(pack2(e.z, e.w), tcc[2 * j + 1]);
            v[2 * j + 1] = unpack2(add2(bq, pack2(l.z, l.w)));
        }
    }
    float best = v[0].x;
    int idx = 0;
#pragma unroll
    for (int k = 0; k < 13; k++) {
        float lo = v[k].x, hi = v[k].y;
        if (k > 0 && lo > best) { best = lo; idx = 2 * k; }
        if (hi > best) { best = hi; idx = 2 * k + 1; }
    }
    return idx;
}

// ---------------------------------------------------------------------------
// Shared layout (bytes) — byte-identical to the twice-verified R8 map:
//   ebuf 3*128*32f = 49152 @0
//   lring 384*32f  = 49152 @49152   (row = i % 384, pointer ring)
//   Ws 128*32f     = 16384 @98304
//   Tt 32*32f      =  4096 @114688
//   bp 2049*32B    = 65568 @118784
//   maps 1024      @184352
//   path 2048      @185376
//   entries 128    @187424
//   total 187552
// ---------------------------------------------------------------------------
#define OFF_EBUF 0
#define OFF_LRING 49152
#define OFF_WS 98304
#define OFF_TT 114688
#define OFF_BP 118784
#define OFF_MAPS 184352
#define OFF_PATH 185376
#define OFF_ENT 187424
#define SMEM_TOTAL 187552

// Warp roles (8 warps):
//   wid 7       : scan warp (hi-wid arbiter priority, SMSP 3)
//   wid 3       : bp-only (lightest role; shares SMSP 3 with the scan warp)
//   wid 0,1,2,4 : emit (1 row/thread, 128 threads) + bp
//   wid 5,6     : bp
__global__ void __launch_bounds__(256, 1) crf_kernel(const float* __restrict__ X,
                                                     const float* __restrict__ W,
                                                     const float* __restrict__ Tm,
                                                     float* __restrict__ out) {
    extern __shared__ unsigned char smx[];
    float* ebuf = (float*)(smx + OFF_EBUF);
    float* lring = (float*)(smx + OFF_LRING);
    float* Ws = (float*)(smx + OFF_WS);
    float* Tt = (float*)(smx + OFF_TT);
    unsigned char* bp = smx + OFF_BP;
    unsigned char* maps = smx + OFF_MAPS;
    unsigned char* path = smx + OFF_PATH;
    int* entries = (int*)(smx + OFF_ENT);

    int tid = threadIdx.x;
    int wid = tid >> 5;
    int lane = tid & 31;
    int b = blockIdx.x;
    const float* Xb = X + (size_t)b * SS * DD;

    bool is_scan = (wid == 7);
    // emit worker row id: warps 0,1,2 -> rows 0..95 ; warp 4 -> rows 96..127
    int ecid = (wid < 3) ? (wid * 32 + lane) : (wid == 4 ? 96 + lane : -1);

    // ---- init ----
    for (int j = tid; j < 128 * 32; j += 256) {
        int k = j >> 5, y = j & 31;
        Ws[j] = (y < YY) ? W[k * YY + y] : 0.f;
    }
    for (int j = tid; j < 32 * 32; j += 256) {
        int ln = j >> 5, yp = j & 31;
        Tt[j] = (ln < YY && yp < YY) ? Tm[yp * YY + ln] : 0.f;
    }
    if (tid < 32) lring[tid] = 0.f;                                  // l[0]=0
    if (tid < 32) bp[2048 * 32 + tid] = (unsigned char)(tid < YY ? tid : 0);
    __syncthreads();

    // ---- prologue: emit tile 0 (warps 0-3, 1 row/thread) ----
    if (tid < 128) emit_row(Xb + (size_t)tid * DD, Ws, ebuf + tid * 32);
    __syncthreads();

    // per-lane T column as packed pairs (scan + bp warps)
    u64 tcc[13];
    {
        const float4* t4 = (const float4*)(Tt + lane * 32);
#pragma unroll
        for (int j = 0; j < 7; j++) {
            float4 t = t4[j];
            tcc[2 * j] = pack2(t.x, t.y);
            if (2 * j + 1 < 13) tcc[2 * j + 1] = pack2(t.z, t.w);
        }
    }

    // scan-warp persistent state: a2 = e[i-1] + Tc; pointer-based l ring
    u64 a2[13];
    float* lw = lring + 32;        // write ptr: row 1
    const float* lr = lring;       // read ptr: row 0
    if (is_scan) {
        const float4* e4 = (const float4*)ebuf;  // e[0]
#pragma unroll
        for (int j = 0; j < 7; j++) {
            float4 e = e4[j];
            a2[2 * j] = add2(pack2(e.x, e.y), tcc[2 * j]);
            if (2 * j + 1 < 13) a2[2 * j + 1] = add2(pack2(e.z, e.w), tcc[2 * j + 1]);
        }
    }

    // =========================== 16 phases ===========================
    for (int p = 0; p < 16; p++) {
        if (is_scan) {
            const float* etb = ebuf + (p % 3) * 4096;
            int i0 = (p == 0) ? 1 : p * 128;
            int i1 = p * 128 + 128;
#pragma unroll 2
            for (int i = i0; i < i1; i++) {
                // v = a + l  (critical chain)
                float2 v[13];
                const float4* l4 = (const float4*)lr;
#pragma unroll
                for (int j = 0; j < 7; j++) {
                    float4 l = l4[j];
                    v[2 * j] = unpack2(add2(a2[2 * j], pack2(l.x, l.y)));
                    if (2 * j + 1 < 13)
                        v[2 * j + 1] = unpack2(add2(a2[2 * j + 1], pack2(l.z, l.w)));
                }
                float m = max26(v);
                lw[lane] = m;  // l[i]
                // a_next = e[i] + Tc (off the chain)
                const float4* e4 = (const float4*)(etb + (i & 127) * 32);
#pragma unroll
                for (int j = 0; j < 7; j++) {
                    float4 e = e4[j];
                    a2[2 * j] = add2(pack2(e.x, e.y), tcc[2 * j]);
                    if (2 * j + 1 < 13)
                        a2[2 * j + 1] = add2(pack2(e.z, e.w), tcc[2 * j + 1]);
                }
                __syncwarp();
                lr = lw;
                lw += 32;
                if (lw == lring + 384 * 32) lw = lring;
            }
        } else {
            // --- all 7 worker warps: bp for tile p-1 (stride 7) ---
            if (p >= 1) {
                int tt = p - 1;
                for (int r = wid; r < 128; r += 7) {
                    int i = tt * 128 + r;
                    if (i > 0) {
                        const float* erow = (r > 0)
                            ? (ebuf + (tt % 3) * 4096 + (r - 1) * 32)
                            : (ebuf + ((tt + 2) % 3) * 4096 + 127 * 32);
                        const float* lrow = lring + ((i - 1) % 384) * 32;
                        int idx = bp_argmax(erow, lrow, tcc);
                        if (lane < YY) bp[i * 32 + lane] = (unsigned char)idx;
                    }
                }
            }
            // boundary e-row reads above must precede the emit overwrite below
            asm volatile("bar.sync 1, 224;" ::: "memory");
            // --- emit warps {0,1,2,4}: tile p+1, 1 row/thread ---
            if (p + 1 < 16 && ecid >= 0) {
                emit_row(Xb + (size_t)((p + 1) * 128 + ecid) * DD, Ws,
                         ebuf + ((p + 1) % 3) * 4096 + ecid * 32);
            }
        }
        __syncthreads();
    }

    // ====================== epilogue ======================
    if (is_scan) {
        // last = argmax(em[2047] + lookup[2047])  (em first, reference order)
        const float4* e4 = (const float4*)(ebuf + 0 * 4096 + 127 * 32);  // tile15->buf0
        const float4* l4 = (const float4*)(lring + 127 * 32);            // 2047%384=127
        float2 vv[13];
#pragma unroll
        for (int j = 0; j < 7; j++) {
            float4 e = e4[j];
            float4 l = l4[j];
            vv[2 * j] = unpack2(add2(pack2(e.x, e.y), pack2(l.x, l.y)));
            if (2 * j + 1 < 13)
                vv[2 * j + 1] = unpack2(add2(pack2(e.z, e.w), pack2(l.z, l.w)));
        }
        float mm; int last;
        argmax26p(vv, mm, last);
        if (lane == 0) entries[31] = last;
    } else {
        // bp for tile 15
        int tt = 15;
        for (int r = wid; r < 128; r += 7) {
            int i = tt * 128 + r;
            const float* erow = (r > 0)
                ? (ebuf + (tt % 3) * 4096 + (r - 1) * 32)
                : (ebuf + ((tt + 2) % 3) * 4096 + 127 * 32);
            const float* lrow = lring + ((i - 1) % 384) * 32;
            int idx = bp_argmax(erow, lrow, tcc);
            if (lane < YY) bp[i * 32 + lane] = (unsigned char)idx;
        }
    }
    __syncthreads();

    // ===== Phase A: per-chunk composed maps (8 warps x 4 chunks of 64) =====
    for (int q = 0; q < 4; q++) {
        int c = wid * 4 + q;
        if (lane < YY) {
            int y = lane;
            int r = (c * 64 + 64) * 32;
            for (int k = 0; k < 64; k++) { y = bp[r + y]; r -= 32; }
            maps[c * 32 + lane] = (unsigned char)y;
        }
    }
    __syncthreads();

    // ===== Phase B: chunk entry labels (serial, 1 thread) =====
    if (tid == 0) {
        int e = entries[31];
        for (int c = 31; c >= 1; c--) {
            e = maps[c * 32 + e];
            entries[c - 1] = e;
        }
    }
    __syncthreads();

    // ===== Phase C: re-chase chunks in parallel (warp 0, 1 chunk/lane) =====
    if (wid == 0) {
        int c = lane;
        int y = entries[c];
        int r = (c * 64 + 64) * 32;
        for (int k = 63; k >= 0; k--) {
            y = bp[r + y];
            r -= 32;
            path[c * 64 + k] = (unsigned char)y;
        }
    }
    __syncthreads();

    // ===== Phase D: one-hot output (256 threads, float2 rows) =====
    float* ob = out + (size_t)b * SS * YY;
    for (int i = tid; i < SS; i += 256) {
        int lbl = path[i];
        float2* orow = (float2*)(ob + (size_t)i * YY);
#pragma unroll
        for (int k = 0; k < 13; k++) {
            float2 w;
            w.x = (2 * k == lbl) ? 1.f : 0.f;
            w.y = (2 * k + 1 == lbl) ? 1.f : 0.f;
            orow[k] = w;
        }
    }
}

// ---------------------------------------------------------------------------
extern "C" void kernel_launch(void* const* d_in, const int* in_sizes, int n_in,
                              void* d_out, int out_size) {
    const float* X = (const float*)d_in[0];   // [B,S,D]
    const float* W = (const float*)d_in[1];   // [D,Y]
    const float* T = (const float*)d_in[2];   // [Y,Y]
    float* out = (float*)d_out;               // [B,S,Y] fp32

    cudaFuncSetAttribute(crf_kernel,
                         cudaFuncAttributeMaxDynamicSharedMemorySize, SMEM_TOTAL);
    crf_kernel<<<BB, 256, SMEM_TOTAL>>>(X, W, T, out);
}

// round 15
// speedup vs baseline: 1.3266x; 1.1497x over previous
#include <cuda_runtime.h>

// Problem constants
#define BB 128
#define SS 2048
#define DD 128
#define YY 26

typedef unsigned long long u64;

// ---- packed f32x2 helpers (each = two independent .rn ops; bit-exact) ----
__device__ __forceinline__ u64 pack2(float x, float y) {
    u64 r; asm("mov.b64 %0, {%1,%2};" : "=l"(r) : "f"(x), "f"(y)); return r;
}
__device__ __forceinline__ float2 unpack2(u64 u) {
    float2 f; asm("mov.b64 {%0,%1}, %2;" : "=f"(f.x), "=f"(f.y) : "l"(u)); return f;
}
__device__ __forceinline__ u64 add2(u64 a, u64 b) {
    u64 d; asm("add.rn.f32x2 %0, %1, %2;" : "=l"(d) : "l"(a), "l"(b)); return d;
}
__device__ __forceinline__ u64 fma2(u64 a, u64 b, u64 c) {
    u64 d; asm("fma.rn.f32x2 %0, %1, %2, %3;" : "=l"(d) : "l"(a), "l"(b), "l"(c)); return d;
}

// ---------------------------------------------------------------------------
// Emit ONE row: e[y] = sum_d x[d]*W[d][y], verified cuBLAS sliced1x4 ordering
// (slice z over chunks k=32t+8z ascending t, FMA ascending k, ((s0+s1)+s2)+s3).
// Weights read as 7 LDS.128 per k-element (bit-exact vs 13-LDS.64 version).
// ---------------------------------------------------------------------------
__device__ __forceinline__ void emit_row(const float* __restrict__ xrow,
                                         const float* __restrict__ Ws,
                                         float* __restrict__ dst) {
    const float4* xr = (const float4*)xrow;
    u64 r2[13], s2[13];
#pragma unroll
    for (int z = 0; z < 4; z++) {
#pragma unroll
        for (int k = 0; k < 13; k++) s2[k] = 0ULL;
#pragma unroll
        for (int t = 0; t < 4; t++) {
            int c = 8 * t + 2 * z;  // float4 index; chunk k = 32t+8z
            float4 xa = xr[c];
            float4 xb = xr[c + 1];
            float xs[8] = {xa.x, xa.y, xa.z, xa.w, xb.x, xb.y, xb.z, xb.w};
#pragma unroll
            for (int kk = 0; kk < 8; kk++) {
                u64 xx = pack2(xs[kk], xs[kk]);
                const float4* w4 = (const float4*)(Ws + (c * 4 + kk) * 32);
#pragma unroll
                for (int q = 0; q < 7; q++) {
                    float4 w = w4[q];
                    s2[2 * q] = fma2(xx, pack2(w.x, w.y), s2[2 * q]);
                    if (2 * q + 1 < 13)
                        s2[2 * q + 1] = fma2(xx, pack2(w.z, w.w), s2[2 * q + 1]);
                }
            }
        }
#pragma unroll
        for (int k = 0; k < 13; k++) r2[k] = (z == 0) ? s2[k] : add2(r2[k], s2[k]);
    }
    float2* d2 = (float2*)dst;
#pragma unroll
    for (int k = 0; k < 13; k++) d2[k] = unpack2(r2[k]);
}

// ---------------------------------------------------------------------------
// Value-only max over 26 (exact; any combine order gives jnp.max bits).
// ---------------------------------------------------------------------------
__device__ __forceinline__ float max26(const float2* v) {
    float m1[13];
#pragma unroll
    for (int k = 0; k < 13; k++) m1[k] = fmaxf(v[k].x, v[k].y);
    float m2[7];
#pragma unroll
    for (int k = 0; k < 6; k++) m2[k] = fmaxf(m1[2 * k], m1[2 * k + 1]);
    m2[6] = m1[12];
    float a = fmaxf(m2[0], m2[1]);
    float b = fmaxf(m2[2], m2[3]);
    float c = fmaxf(m2[4], m2[5]);
    return fmaxf(fmaxf(a, b), fmaxf(c, m2[6]));
}

// Full first-index argmax (keep-left on >=, left covers lower indices).
__device__ __forceinline__ void argmax26p(const float2* v2, float& mv, int& mi) {
    float m1[13]; int i1[13];
#pragma unroll
    for (int k = 0; k < 13; k++) {
        float lo = v2[k].x, hi = v2[k].y;
        m1[k] = fmaxf(lo, hi);
        i1[k] = (lo >= hi) ? (2 * k) : (2 * k + 1);
    }
    float m2[7]; int i2[7];
#pragma unroll
    for (int k = 0; k < 6; k++) {
        m2[k] = fmaxf(m1[2 * k], m1[2 * k + 1]);
        i2[k] = (m1[2 * k] >= m1[2 * k + 1]) ? i1[2 * k] : i1[2 * k + 1];
    }
    m2[6] = m1[12]; i2[6] = i1[12];
    float m3[4]; int i3[4];
#pragma unroll
    for (int k = 0; k < 3; k++) {
        m3[k] = fmaxf(m2[2 * k], m2[2 * k + 1]);
        i3[k] = (m2[2 * k] >= m2[2 * k + 1]) ? i2[2 * k] : i2[2 * k + 1];
    }
    m3[3] = m2[6]; i3[3] = i2[6];
    float a = fmaxf(m3[0], m3[1]);
    int ia = (m3[0] >= m3[1]) ? i3[0] : i3[1];
    float bq = fmaxf(m3[2], m3[3]);
    int ib = (m3[2] >= m3[3]) ? i3[2] : i3[3];
    mv = fmaxf(a, bq);
    mi = (a >= bq) ? ia : ib;
}

// ---------------------------------------------------------------------------
// bp for one (i, y1=lane): first-index argmax over yp of (e[yp]+T[yp][y1])+l[yp]
// Serial ascending scan with strict > == jnp.argmax first-occurrence.
// ---------------------------------------------------------------------------
__device__ __forceinline__ int bp_argmax(const float* __restrict__ erow,
                                         const float* __restrict__ lrow,
                                         const u64* __restrict__ tcc) {
    float2 v[13];
    const float4* e4 = (const float4*)erow;
    const float4* l4 = (const float4*)lrow;
#pragma unroll
    for (int j = 0; j < 7; j++) {
        float4 e = e4[j];
        float4 l = l4[j];
        u64 a = add2(pack2(e.x, e.y), tcc[2 * j]);
        v[2 * j] = unpack2(add2(a, pack2(l.x, l.y)));
        if (2 * j + 1 < 13) {
            u64 bq = add2(pack2(e.z, e.w), tcc[2 * j + 1]);
            v[2 * j + 1] = unpack2(add2(bq, pack2(l.z, l.w)));
        }
    }
    float best = v[0].x;
    int idx = 0;
#pragma unroll
    for (int k = 0; k < 13; k++) {
        float lo = v[k].x, hi = v[k].y;
        if (k > 0 && lo > best) { best = lo; idx = 2 * k; }
        if (hi > best) { best = hi; idx = 2 * k + 1; }
    }
    return idx;
}

// ---------------------------------------------------------------------------
// Shared layout (bytes) — byte-identical to the verified R8/R13 map:
//   ebuf 3*128*32f = 49152 @0
//   lring 384*32f  = 49152 @49152   (row = i % 384; 384%128==0 -> contiguous per tile)
//   Ws 128*32f     = 16384 @98304
//   Tt 32*32f      =  4096 @114688
//   bp 2049*32B    = 65568 @118784
//   maps 1024      @184352
//   path 2048      @185376
//   entries 128    @187424
//   total 187552
// ---------------------------------------------------------------------------
#define OFF_EBUF 0
#define OFF_LRING 49152
#define OFF_WS 98304
#define OFF_TT 114688
#define OFF_BP 118784
#define OFF_MAPS 184352
#define OFF_PATH 185376
#define OFF_ENT 187424
#define SMEM_TOTAL 187552

// Warp roles (8 warps):
//   wid 7       : scan warp (hi-wid arbiter priority, SMSP 3)
//   wid 3       : bp-only (lightest role; shares SMSP 3 with the scan warp)
//   wid 0,1,2,4 : emit (1 row/thread, 128 threads) + bp
//   wid 5,6     : bp
__global__ void __launch_bounds__(256, 1) crf_kernel(const float* __restrict__ X,
                                                     const float* __restrict__ W,
                                                     const float* __restrict__ Tm,
                                                     float* __restrict__ out) {
    extern __shared__ unsigned char smx[];
    float* ebuf = (float*)(smx + OFF_EBUF);
    float* lring = (float*)(smx + OFF_LRING);
    float* Ws = (float*)(smx + OFF_WS);
    float* Tt = (float*)(smx + OFF_TT);
    unsigned char* bp = smx + OFF_BP;
    unsigned char* maps = smx + OFF_MAPS;
    unsigned char* path = smx + OFF_PATH;
    int* entries = (int*)(smx + OFF_ENT);

    int tid = threadIdx.x;
    int wid = tid >> 5;
    int lane = tid & 31;
    int b = blockIdx.x;
    const float* Xb = X + (size_t)b * SS * DD;

    bool is_scan = (wid == 7);
    // emit worker row id: warps 0,1,2 -> rows 0..95 ; warp 4 -> rows 96..127
    int ecid = (wid < 3) ? (wid * 32 + lane) : (wid == 4 ? 96 + lane : -1);

    // ---- init ----
    for (int j = tid; j < 128 * 32; j += 256) {
        int k = j >> 5, y = j & 31;
        Ws[j] = (y < YY) ? W[k * YY + y] : 0.f;
    }
    for (int j = tid; j < 32 * 32; j += 256) {
        int ln = j >> 5, yp = j & 31;
        Tt[j] = (ln < YY && yp < YY) ? Tm[yp * YY + ln] : 0.f;
    }
    if (tid < 32) lring[tid] = 0.f;                                  // l[0]=0
    if (tid < 32) bp[2048 * 32 + tid] = (unsigned char)(tid < YY ? tid : 0);
    __syncthreads();

    // ---- prologue: emit tile 0 (tid<128, 1 row/thread) ----
    if (tid < 128) emit_row(Xb + (size_t)tid * DD, Ws, ebuf + tid * 32);
    __syncthreads();

    // per-lane T column as packed pairs (scan + bp warps)
    u64 tcc[13];
    {
        const float4* t4 = (const float4*)(Tt + lane * 32);
#pragma unroll
        for (int j = 0; j < 7; j++) {
            float4 t = t4[j];
            tcc[2 * j] = pack2(t.x, t.y);
            if (2 * j + 1 < 13) tcc[2 * j + 1] = pack2(t.z, t.w);
        }
    }

    // scan-warp persistent state: a2 = e[i-1]+Tc ; lc = l[i-1] (registers)
    u64 a2[13];
    float4 lc[7];
    if (is_scan) {
        const float4* e4 = (const float4*)ebuf;  // e[0]
#pragma unroll
        for (int j = 0; j < 7; j++) {
            float4 e = e4[j];
            a2[2 * j] = add2(pack2(e.x, e.y), tcc[2 * j]);
            if (2 * j + 1 < 13) a2[2 * j + 1] = add2(pack2(e.z, e.w), tcc[2 * j + 1]);
        }
        const float4* l4 = (const float4*)lring;  // l[0] = zeros
#pragma unroll
        for (int j = 0; j < 7; j++) lc[j] = l4[j];
    }

    // =========================== 16 phases ===========================
    for (int p = 0; p < 16; p++) {
        if (is_scan) {
            const float* etb = ebuf + (p % 3) * 4096;
            float* wbase = lring + ((p * 128) % 384) * 32;  // contiguous rows
            int k0 = (p == 0) ? 1 : 0;
#pragma unroll 4
            for (int k = k0; k < 128; k++) {
                float* wrow = wbase + k * 32;
                // v = a2 + lc  (critical chain; lc in registers)
                float2 v[13];
#pragma unroll
                for (int j = 0; j < 7; j++) {
                    v[2 * j] = unpack2(add2(a2[2 * j], pack2(lc[j].x, lc[j].y)));
                    if (2 * j + 1 < 13)
                        v[2 * j + 1] = unpack2(add2(a2[2 * j + 1], pack2(lc[j].z, lc[j].w)));
                }
                float m = max26(v);
                wrow[lane] = m;  // STS l[i]
                asm volatile("" ::: "memory");  // keep LDS after STS (codegen order)
                // reload the just-written row (latency hidden under a_next)
                const float4* wr4 = (const float4*)wrow;
#pragma unroll
                for (int j = 0; j < 7; j++) lc[j] = wr4[j];
                // a_next = e[i] + Tc  (off the chain)
                const float4* e4 = (const float4*)(etb + k * 32);
#pragma unroll
                for (int j = 0; j < 7; j++) {
                    float4 e = e4[j];
                    a2[2 * j] = add2(pack2(e.x, e.y), tcc[2 * j]);
                    if (2 * j + 1 < 13)
                        a2[2 * j + 1] = add2(pack2(e.z, e.w), tcc[2 * j + 1]);
                }
            }
        } else {
            // --- all 7 worker warps: bp for tile p-1 (stride 7) ---
            if (p >= 1) {
                int tt = p - 1;
                for (int r = wid; r < 128; r += 7) {
                    int i = tt * 128 + r;
                    if (i > 0) {
                        const float* erow = (r > 0)
                            ? (ebuf + (tt % 3) * 4096 + (r - 1) * 32)
                            : (ebuf + ((tt + 2) % 3) * 4096 + 127 * 32);
                        const float* lrow = lring + ((i - 1) % 384) * 32;
                        int idx = bp_argmax(erow, lrow, tcc);
                        if (lane < YY) bp[i * 32 + lane] = (unsigned char)idx;
                    }
                }
            }
            // boundary e-row reads above must precede the emit overwrite below
            asm volatile("bar.sync 1, 224;" ::: "memory");
            // --- emit warps {0,1,2,4}: tile p+1, 1 row/thread ---
            if (p + 1 < 16 && ecid >= 0) {
                emit_row(Xb + (size_t)((p + 1) * 128 + ecid) * DD, Ws,
                         ebuf + ((p + 1) % 3) * 4096 + ecid * 32);
            }
        }
        __syncthreads();
    }

    // ====================== epilogue ======================
    if (is_scan) {
        // last = argmax(em[2047] + lookup[2047])  (em first, reference order)
        const float4* e4 = (const float4*)(ebuf + 0 * 4096 + 127 * 32);  // tile15->buf0
        const float4* l4 = (const float4*)(lring + 127 * 32);            // 2047%384=127
        float2 vv[13];
#pragma unroll
        for (int j = 0; j < 7; j++) {
            float4 e = e4[j];
            float4 l = l4[j];
            vv[2 * j] = unpack2(add2(pack2(e.x, e.y), pack2(l.x, l.y)));
            if (2 * j + 1 < 13)
                vv[2 * j + 1] = unpack2(add2(pack2(e.z, e.w), pack2(l.z, l.w)));
        }
        float mm; int last;
        argmax26p(vv, mm, last);
        if (lane == 0) entries[31] = last;
    } else {
        // bp for tile 15
        int tt = 15;
        for (int r = wid; r < 128; r += 7) {
            int i = tt * 128 + r;
            const float* erow = (r > 0)
                ? (ebuf + (tt % 3) * 4096 + (r - 1) * 32)
                : (ebuf + ((tt + 2) % 3) * 4096 + 127 * 32);
            const float* lrow = lring + ((i - 1) % 384) * 32;
            int idx = bp_argmax(erow, lrow, tcc);
            if (lane < YY) bp[i * 32 + lane] = (unsigned char)idx;
        }
    }
    __syncthreads();

    // ===== Phase A: per-chunk composed maps (8 warps x 4 chunks of 64) =====
    for (int q = 0; q < 4; q++) {
        int c = wid * 4 + q;
        if (lane < YY) {
            int y = lane;
            int r = (c * 64 + 64) * 32;
            for (int k = 0; k < 64; k++) { y = bp[r + y]; r -= 32; }
            maps[c * 32 + lane] = (unsigned char)y;
        }
    }
    __syncthreads();

    // ===== Phase B: chunk entry labels (serial, 1 thread) =====
    if (tid == 0) {
        int e = entries[31];
        for (int c = 31; c >= 1; c--) {
            e = maps[c * 32 + e];
            entries[c - 1] = e;
        }
    }
    __syncthreads();

    // ===== Phase C: re-chase chunks in parallel (warp 0, 1 chunk/lane) =====
    if (wid == 0) {
        int c = lane;
        int y = entries[c];
        int r = (c * 64 + 64) * 32;
        for (int k = 63; k >= 0; k--) {
            y = bp[r + y];
            r -= 32;
            path[c * 64 + k] = (unsigned char)y;
        }
    }
    __syncthreads();

    // ===== Phase D: one-hot output (256 threads, float2 rows) =====
    float* ob = out + (size_t)b * SS * YY;
    for (int i = tid; i < SS; i += 256) {
        int lbl = path[i];
        float2* orow = (float2*)(ob + (size_t)i * YY);
#pragma unroll
        for (int k = 0; k < 13; k++) {
            float2 w;
            w.x = (2 * k == lbl) ? 1.f : 0.f;
            w.y = (2 * k + 1 == lbl) ? 1.f : 0.f;
            orow[k] = w;
        }
    }
}

// ---------------------------------------------------------------------------
extern "C" void kernel_launch(void* const* d_in, const int* in_sizes, int n_in,
                              void* d_out, int out_size) {
    const float* X = (const float*)d_in[0];   // [B,S,D]
    const float* W = (const float*)d_in[1];   // [D,Y]
    const float* T = (const float*)d_in[2];   // [Y,Y]
    float* out = (float*)d_out;               // [B,S,Y] fp32

    cudaFuncSetAttribute(crf_kernel,
                         cudaFuncAttributeMaxDynamicSharedMemorySize, SMEM_TOTAL);
    crf_kernel<<<BB, 256, SMEM_TOTAL>>>(X, W, T, out);
}